// round 15
// baseline (speedup 1.0000x reference)
#include <cuda_runtime.h>

// ---------------- problem constants ----------------------------------------
#define BGRAPH 1024
#define FN     32
#define DIN    64
#define HID    128
#define NHEADS 4
#define EPG    256
#define ETOT   (EPG + FN)       // 288
#define H4     (NHEADS * HID)   // 512
#define XPAD   128
#define YTPAD  36              // 16B-aligned row-pair groups
#define ETPAD  34
#define A1PAD  36              // 16B-aligned d-octet groups
#define NTH    512

// ---------------- shared memory layout (float offsets) ---------------------
#define SM_YT   0                      // yT [4][128][36] = 18432
                                       //   overlays: embT [64][34] (P0-P1);
                                       //   zbp [4][512] | zb2 [512 ull] |
                                       //   ps2 [1024]   (post-P5)
#define SM_X    18432                  // X [32][128] = 4096
#define SM_A1   22528                  // [4][32][36] = 4608
#define SM_LB   27136                  // 288
#define SM_AS1  27424                  // 128
#define SM_AD1  27552                  // 128
#define SM_AS2  27680                  // 32
#define SM_AD2  27712                  // 32
#define SM_DN2  27744                  // 32
#define SM_CSR  27776                  // 32
#define SM_NF   27808
#define SM_NI   (2 * ETOT)             // 576 ints
#define SMEM_BYTES ((SM_NF + SM_NI) * 4)   // 113,536 B -> 2 CTAs/SM

typedef unsigned long long ull;

__device__ float g_wts1[512];
__device__ float g_wtd1[512];
__device__ float g_wt2s[512];
__device__ float g_wt2d[512];

__device__ __forceinline__ ull pk2(float x, float y) {
    ull r; asm("mov.b64 %0, {%1,%2};" : "=l"(r) : "f"(x), "f"(y)); return r;
}
__device__ __forceinline__ ull splat2(float x) { return pk2(x, x); }
__device__ __forceinline__ void upk2(ull p, float& x, float& y) {
    asm("mov.b64 {%0,%1}, %2;" : "=f"(x), "=f"(y) : "l"(p));
}
__device__ __forceinline__ void fma2(ull& d, ull a, ull b) {
    asm("fma.rn.f32x2 %0, %1, %2, %0;" : "+l"(d) : "l"(a), "l"(b));
}
__device__ __forceinline__ void mul2(ull& d, ull b) {
    asm("mul.rn.f32x2 %0, %0, %1;" : "+l"(d) : "l"(b));
}
__device__ __forceinline__ ull add2(ull a, ull b) {
    ull r; asm("add.rn.f32x2 %0, %1, %2;" : "=l"(r) : "l"(a), "l"(b)); return r;
}
__device__ __forceinline__ float dot4(const float4& a, const float4& b) {
    return fmaf(a.x, b.x, fmaf(a.y, b.y, fmaf(a.z, b.z, a.w * b.w)));
}
__device__ __forceinline__ float wredsum(float v) {
    #pragma unroll
    for (int o = 16; o; o >>= 1) v += __shfl_xor_sync(0xffffffffu, v, o);
    return v;
}
__device__ __forceinline__ float elu1(float x) {
    return (x > 0.f) ? x : expm1f(x);
}

// ---------------- pre-kernel: warp-parallel attention-weight projection ----
__global__ void precomp_kernel(const float* __restrict__ W1,
                               const float* __restrict__ as1w,
                               const float* __restrict__ ad1w,
                               const float* __restrict__ W2,
                               const float* __restrict__ as2w,
                               const float* __restrict__ ad2w)
{
    int idx  = blockIdx.x * 4 + (threadIdx.x >> 5);   // 0..1023
    int lane = threadIdx.x & 31;
    if (idx < 512) {
        int h = idx >> 7, k = idx & 127;
        float4 w = ((const float4*)(W1 + k * H4 + h * HID))[lane];
        float4 a = ((const float4*)(as1w + h * HID))[lane];
        float4 d = ((const float4*)(ad1w + h * HID))[lane];
        float s  = wredsum(dot4(w, a));
        float dd = wredsum(dot4(w, d));
        if (lane == 0) { g_wts1[idx] = s; g_wtd1[idx] = dd; }
    } else {
        int k = idx - 512;
        float4 w = ((const float4*)(W2 + k * HID))[lane];
        float4 a = ((const float4*)as2w)[lane];
        float4 d = ((const float4*)ad2w)[lane];
        float s  = wredsum(dot4(w, a));
        float dd = wredsum(dot4(w, d));
        if (lane == 0) { g_wt2s[k] = s; g_wt2d[k] = dd; }
    }
}

__global__ __launch_bounds__(NTH, 2)
void gat_fused_kernel(
    const float* __restrict__ emb,    const float* __restrict__ Wal,
    const float* __restrict__ bal,    const float* __restrict__ lng,
    const float* __restrict__ lnb,    const float* __restrict__ gatel,
    const float* __restrict__ W1,     const float* __restrict__ b1,
    const float* __restrict__ W2,     const float* __restrict__ b2,
    const int*   __restrict__ esrc,   const int*   __restrict__ edst,
    float*       __restrict__ out,    int write_gate)
{
    extern __shared__ float sm[];
    float* yT   = sm + SM_YT;             // [4][128][36]
    float* embT = sm + SM_YT;             // [64][34] overlay
    float* zbp  = sm + SM_YT;             // [4][512] overlay (post-P5)
    ull*   zb2  = (ull*)(sm + SM_YT + 2048);   // [512] dup pairs
    float* ps2  = sm + SM_YT + 3072;      // [1024] overlay (post-P5)
    float* X    = sm + SM_X;              // [32][128]
    float* A1   = sm + SM_A1;
    float* lbuf = sm + SM_LB;
    float* as1  = sm + SM_AS1;
    float* ad1  = sm + SM_AD1;
    float* as2  = sm + SM_AS2;
    float* ad2  = sm + SM_AD2;
    float* dn2  = sm + SM_DN2;
    float* csr  = sm + SM_CSR;
    int* sSL = (int*)(sm + SM_NF);
    int* sDL = sSL + ETOT;

    const int g    = blockIdx.x;
    const int tid  = threadIdx.x;
    const int lane = tid & 31;
    const int wid  = tid >> 5;

    // ---------- Phase 0: stage embT + edges, zero accumulators -------------
    {
        float4 v = ((const float4*)emb)[(size_t)g * (FN * DIN / 4) + tid];
        int r  = tid >> 4;
        int c4 = tid & 15;
        embT[(c4 * 4 + 0) * ETPAD + r] = v.x;
        embT[(c4 * 4 + 1) * ETPAD + r] = v.y;
        embT[(c4 * 4 + 2) * ETPAD + r] = v.z;
        embT[(c4 * 4 + 3) * ETPAD + r] = v.w;
    }
    if (tid < 256) {
        sSL[tid] = esrc[g * EPG + tid] - g * FN;
        sDL[tid] = edst[g * EPG + tid] - g * FN;
    }
    if (tid < 32) {
        sSL[EPG + tid] = tid;  sDL[EPG + tid] = tid;   // self loops
        as2[tid] = 0.f; ad2[tid] = 0.f; dn2[tid] = 0.f; csr[tid] = 0.f;
    }
    for (int i = tid; i < (4 * FN * A1PAD) / 4; i += NTH)
        ((float4*)A1)[i] = make_float4(0.f, 0.f, 0.f, 0.f);
    __syncthreads();

    // ---------- Phase 1: align GEMM + in-register LN/gate/logits1 ----------
    {
        ull acc[4];
        #pragma unroll
        for (int j = 0; j < 4; ++j) acc[j] = 0ULL;
        const float4* Wp = (const float4*)Wal + lane;
        #pragma unroll 4
        for (int k = 0; k < DIN; ++k) {
            float4 b = Wp[k * 32];
            ull a0 = *(const ull*)(embT + k * ETPAD + wid * 2);
            fma2(acc[0], a0, splat2(b.x));
            fma2(acc[1], a0, splat2(b.y));
            fma2(acc[2], a0, splat2(b.z));
            fma2(acc[3], a0, splat2(b.w));
        }
        float4 bb = ((const float4*)bal)[lane];
        float4 r0, r1;
        upk2(acc[0], r0.x, r1.x); upk2(acc[1], r0.y, r1.y);
        upk2(acc[2], r0.z, r1.z); upk2(acc[3], r0.w, r1.w);
        r0.x += bb.x; r0.y += bb.y; r0.z += bb.z; r0.w += bb.w;
        r1.x += bb.x; r1.y += bb.y; r1.z += bb.z; r1.w += bb.w;
        float4 lg = ((const float4*)lng)[lane];
        float4 lb = ((const float4*)lnb)[lane];
        const int row0 = wid * 2;
        float s0 = wredsum(r0.x + r0.y + r0.z + r0.w);
        float q0 = wredsum(dot4(r0, r0));
        float s1 = wredsum(r1.x + r1.y + r1.z + r1.w);
        float q1 = wredsum(dot4(r1, r1));
        float m0 = s0 * (1.f / HID);
        float m1 = s1 * (1.f / HID);
        float rs0 = rsqrtf(q0 * (1.f / HID) - m0 * m0 + 1e-5f);
        float rs1 = rsqrtf(q1 * (1.f / HID) - m1 * m1 + 1e-5f);
        float g0 = 1.f / (1.f + __expf(-gatel[row0]));
        float g1 = 1.f / (1.f + __expf(-gatel[row0 + 1]));
        float4 x0, x1;
        x0.x = ((r0.x - m0) * rs0 * lg.x + lb.x) * g0;
        x0.y = ((r0.y - m0) * rs0 * lg.y + lb.y) * g0;
        x0.z = ((r0.z - m0) * rs0 * lg.z + lb.z) * g0;
        x0.w = ((r0.w - m0) * rs0 * lg.w + lb.w) * g0;
        x1.x = ((r1.x - m1) * rs1 * lg.x + lb.x) * g1;
        x1.y = ((r1.y - m1) * rs1 * lg.y + lb.y) * g1;
        x1.z = ((r1.z - m1) * rs1 * lg.z + lb.z) * g1;
        x1.w = ((r1.w - m1) * rs1 * lg.w + lb.w) * g1;
        ((float4*)(X + row0 * XPAD))[lane]       = x0;
        ((float4*)(X + (row0 + 1) * XPAD))[lane] = x1;
        #pragma unroll
        for (int h = 0; h < NHEADS; ++h) {
            float4 ws = ((const float4*)g_wts1)[h * 32 + lane];
            float4 wd = ((const float4*)g_wtd1)[h * 32 + lane];
            float a0s = wredsum(dot4(x0, ws));
            float a0d = wredsum(dot4(x0, wd));
            float a1s = wredsum(dot4(x1, ws));
            float a1d = wredsum(dot4(x1, wd));
            if (lane == 0) {
                as1[row0 * 4 + h] = a0s;       ad1[row0 * 4 + h] = a0d;
                as1[(row0 + 1) * 4 + h] = a1s; ad1[(row0 + 1) * 4 + h] = a1d;
            }
        }
    }
    __syncthreads();

    // ---------- Phase 3: edge pass 1 -> dense A1 ---------------------------
    {
        int h = tid & 3;
        for (int e = tid >> 2; e < ETOT; e += 128) {
            int s = sSL[e], d = sDL[e];
            float l = as1[s * 4 + h] + ad1[d * 4 + h];
            l = (l > 0.f) ? l : 0.2f * l;
            atomicAdd(&A1[(h * FN + s) * A1PAD + d], __expf(l));
        }
    }
    __syncthreads();

    // ---------- Phase 4: y = A1n^T @ x (16 warps, inline inv1) -> yT -------
    {
        const int h  = wid >> 2;
        const int dg = wid & 3;
        int myd = dg * 8 + (lane & 7);
        float csum = 0.f;
        #pragma unroll 8
        for (int s = 0; s < FN; ++s) csum += A1[(h * FN + s) * A1PAD + myd];
        float myinv = __fdividef(1.f, csum);
        ull acc[4][4];                       // [q][dp]
        #pragma unroll
        for (int q = 0; q < 4; ++q)
            #pragma unroll
            for (int dp = 0; dp < 4; ++dp) acc[q][dp] = 0ULL;
        #pragma unroll 2
        for (int s = 0; s < FN; ++s) {
            const ulonglong2* arp =
                (const ulonglong2*)(A1 + (h * FN + s) * A1PAD + dg * 8);
            ulonglong2 a01 = arp[0];
            ulonglong2 a23 = arp[1];
            ull a0 = a01.x, a1 = a01.y, a2 = a23.x, a3 = a23.y;
            const float* xr = X + s * XPAD + lane;
            ull x0 = splat2(xr[0]);
            ull x1 = splat2(xr[32]);
            ull x2 = splat2(xr[64]);
            ull x3 = splat2(xr[96]);
            fma2(acc[0][0], a0, x0); fma2(acc[0][1], a1, x0);
            fma2(acc[0][2], a2, x0); fma2(acc[0][3], a3, x0);
            fma2(acc[1][0], a0, x1); fma2(acc[1][1], a1, x1);
            fma2(acc[1][2], a2, x1); fma2(acc[1][3], a3, x1);
            fma2(acc[2][0], a0, x2); fma2(acc[2][1], a1, x2);
            fma2(acc[2][2], a2, x2); fma2(acc[2][3], a3, x2);
            fma2(acc[3][0], a0, x3); fma2(acc[3][1], a1, x3);
            fma2(acc[3][2], a2, x3); fma2(acc[3][3], a3, x3);
        }
        ull iv[4];
        #pragma unroll
        for (int dp = 0; dp < 4; ++dp) {
            float i0 = __shfl_sync(0xffffffffu, myinv, 2 * dp);
            float i1 = __shfl_sync(0xffffffffu, myinv, 2 * dp + 1);
            iv[dp] = pk2(i0, i1);
        }
        #pragma unroll
        for (int q = 0; q < 4; ++q) {
            int k = lane + 32 * q;
            float* yb = yT + (h * HID + k) * YTPAD + dg * 8;
            #pragma unroll
            for (int dp = 0; dp < 4; ++dp) mul2(acc[q][dp], iv[dp]);
            ulonglong2 v01, v23;
            v01.x = acc[q][0]; v01.y = acc[q][1];
            v23.x = acc[q][2]; v23.y = acc[q][3];
            ((ulonglong2*)yb)[0] = v01;
            ((ulonglong2*)yb)[1] = v23;
        }
    }
    __syncthreads();

    // ---------- Phase 5: h1 = ELU(y @ W1 + b1) in REGISTERS ----------------
    // 16 warps: warp = (rg, h), 8 rows x 128 cols; acc[p][j] holds rows
    // (rg*8+2p, +1) for column h*128 + lane*4 + j.
    ull acc[4][4];
    {
        const int rg = wid >> 2;
        const int h  = wid & 3;
        #pragma unroll
        for (int p = 0; p < 4; ++p)
            #pragma unroll
            for (int j = 0; j < 4; ++j) acc[p][j] = 0ULL;
        const float4* Wp = (const float4*)W1 + h * 32 + lane;
        const float* yh = yT + h * HID * YTPAD + rg * 8;
        #pragma unroll 2
        for (int k = 0; k < HID; ++k) {
            float4 w = Wp[k * 128];
            ull b0 = splat2(w.x), b1v = splat2(w.y);
            ull b2v = splat2(w.z), b3 = splat2(w.w);
            const ulonglong2* yp = (const ulonglong2*)(yh + k * YTPAD);
            ulonglong2 y01 = yp[0];
            ulonglong2 y23 = yp[1];
            fma2(acc[0][0], y01.x, b0); fma2(acc[0][1], y01.x, b1v);
            fma2(acc[0][2], y01.x, b2v); fma2(acc[0][3], y01.x, b3);
            fma2(acc[1][0], y01.y, b0); fma2(acc[1][1], y01.y, b1v);
            fma2(acc[1][2], y01.y, b2v); fma2(acc[1][3], y01.y, b3);
            fma2(acc[2][0], y23.x, b0); fma2(acc[2][1], y23.x, b1v);
            fma2(acc[2][2], y23.x, b2v); fma2(acc[2][3], y23.x, b3);
            fma2(acc[3][0], y23.y, b0); fma2(acc[3][1], y23.y, b1v);
            fma2(acc[3][2], y23.y, b2v); fma2(acc[3][3], y23.y, b3);
        }
        float4 bb  = ((const float4*)b1)[h * 32 + lane];
        float4 w2s = ((const float4*)g_wt2s)[h * 32 + lane];
        float4 w2d = ((const float4*)g_wt2d)[h * 32 + lane];
        #pragma unroll
        for (int p = 0; p < 4; ++p) {
            int d0 = rg * 8 + p * 2;
            float4 r0, r1;
            upk2(acc[p][0], r0.x, r1.x); upk2(acc[p][1], r0.y, r1.y);
            upk2(acc[p][2], r0.z, r1.z); upk2(acc[p][3], r0.w, r1.w);
            r0.x = elu1(r0.x + bb.x); r0.y = elu1(r0.y + bb.y);
            r0.z = elu1(r0.z + bb.z); r0.w = elu1(r0.w + bb.w);
            r1.x = elu1(r1.x + bb.x); r1.y = elu1(r1.y + bb.y);
            r1.z = elu1(r1.z + bb.z); r1.w = elu1(r1.w + bb.w);
            acc[p][0] = pk2(r0.x, r1.x);
            acc[p][1] = pk2(r0.y, r1.y);
            acc[p][2] = pk2(r0.z, r1.z);
            acc[p][3] = pk2(r0.w, r1.w);
            float s0  = wredsum(dot4(r0, w2s));
            float d0s = wredsum(dot4(r0, w2d));
            float s1  = wredsum(dot4(r1, w2s));
            float d1s = wredsum(dot4(r1, w2d));
            if (lane == 0) {
                atomicAdd(&as2[d0], s0);
                atomicAdd(&ad2[d0], d0s);
                atomicAdd(&as2[d0 + 1], s1);
                atomicAdd(&ad2[d0 + 1], d1s);
            }
        }
    }
    __syncthreads();

    // ---------- Phase 6: edge pass 2 -> csr (merged iv2) -------------------
    if (tid < ETOT) {
        int s = sSL[tid], d = sDL[tid];
        float l = as2[s] + ad2[d];
        l = (l > 0.f) ? l : 0.2f * l;
        float ex = __expf(l);
        lbuf[tid] = ex;
        atomicAdd(&dn2[d], ex);
    }
    __syncthreads();
    if (tid < ETOT) {
        int s = sSL[tid], d = sDL[tid];
        atomicAdd(&csr[s], lbuf[tid] * __fdividef(1.f, dn2[d] * (float)FN));
    }
    __syncthreads();

    // ---------- Phase 7': zb partials from register-resident h1 ------------
    {
        const int rg = wid >> 2;
        const int h  = wid & 3;
        ull csrp[4];
        #pragma unroll
        for (int p = 0; p < 4; ++p)
            csrp[p] = pk2(csr[rg * 8 + 2 * p], csr[rg * 8 + 2 * p + 1]);
        float4 zp4;
        float* zv = &zp4.x;
        #pragma unroll
        for (int j = 0; j < 4; ++j) {
            ull za = 0ULL;
            #pragma unroll
            for (int p = 0; p < 4; ++p) fma2(za, csrp[p], acc[p][j]);
            float lo, hi;
            upk2(za, lo, hi);
            zv[j] = lo + hi;
        }
        ((float4*)(zbp + rg * 512 + h * HID))[lane] = zp4;
    }
    __syncthreads();
    {
        float v = zbp[tid] + zbp[512 + tid] + zbp[1024 + tid] + zbp[1536 + tid];
        zb2[tid] = pk2(v, v);               // duplicated pair for P8
    }
    __syncthreads();

    // ---------- Phase 8: out = zbar @ W2 + b2 (f32x2 col-pairs, 8 ks) ------
    {
        const int ks = tid >> 6;             // 8 k-splits of 64
        const int cp = tid & 63;             // column pair
        const float* w2 = W2 + (ks * 64) * HID + cp * 2;
        const ull* zp2 = zb2 + ks * 64;
        ull a0 = 0ULL, a1 = 0ULL, a2 = 0ULL, a3 = 0ULL;
        #pragma unroll 4
        for (int k = 0; k < 64; k += 4) {
            fma2(a0, zp2[k + 0], *(const ull*)(w2 + (k + 0) * HID));
            fma2(a1, zp2[k + 1], *(const ull*)(w2 + (k + 1) * HID));
            fma2(a2, zp2[k + 2], *(const ull*)(w2 + (k + 2) * HID));
            fma2(a3, zp2[k + 3], *(const ull*)(w2 + (k + 3) * HID));
        }
        ull tot = add2(add2(a0, a1), add2(a2, a3));
        *(ull*)(ps2 + tid * 2) = tot;        // ps2[ks*128 + c] = partial(c)
    }
    __syncthreads();
    if (tid < HID) {
        float tot = 0.f;
        #pragma unroll
        for (int q = 0; q < 8; ++q) tot += ps2[q * 128 + tid];
        out[(size_t)g * HID + tid] = tot + b2[tid];
    }
    if (write_gate && g == 0 && tid < FN) {
        out[(size_t)BGRAPH * HID + tid] = 1.f / (1.f + __expf(-gatel[tid]));
    }
}

extern "C" void kernel_launch(void* const* d_in, const int* in_sizes, int n_in,
                              void* d_out, int out_size)
{
    const float* emb   = (const float*)d_in[0];
    const float* Wal   = (const float*)d_in[1];
    const float* bal   = (const float*)d_in[2];
    const float* lng   = (const float*)d_in[3];
    const float* lnb   = (const float*)d_in[4];
    const float* gatel = (const float*)d_in[5];
    const float* W1    = (const float*)d_in[6];
    const float* as1w  = (const float*)d_in[7];
    const float* ad1w  = (const float*)d_in[8];
    const float* b1    = (const float*)d_in[9];
    const float* W2    = (const float*)d_in[10];
    const float* as2w  = (const float*)d_in[11];
    const float* ad2w  = (const float*)d_in[12];
    const float* b2    = (const float*)d_in[13];
    const int*   ei    = (const int*)d_in[14];

    const int Et = in_sizes[14] / 2;
    const int* esrc = ei;
    const int* edst = ei + Et;
    const int write_gate = (out_size >= BGRAPH * HID + FN) ? 1 : 0;

    cudaFuncSetAttribute(gat_fused_kernel,
                         cudaFuncAttributeMaxDynamicSharedMemorySize, SMEM_BYTES);

    precomp_kernel<<<256, 128>>>(W1, as1w, ad1w, W2, as2w, ad2w);
    gat_fused_kernel<<<BGRAPH, NTH, SMEM_BYTES>>>(
        emb, Wal, bal, lng, lnb, gatel,
        W1, b1, W2, b2,
        esrc, edst, (float*)d_out, write_gate);
}

// round 16
// speedup vs baseline: 1.0525x; 1.0525x over previous
#include <cuda_runtime.h>

// ---------------- problem constants ----------------------------------------
#define BGRAPH 1024
#define FN     32
#define DIN    64
#define HID    128
#define NHEADS 4
#define EPG    256
#define ETOT   (EPG + FN)       // 288
#define H4     (NHEADS * HID)   // 512
#define XPAD   128
#define YTPAD  36              // 16B-aligned row-pair groups
#define ETPAD  34
#define A1PAD  34
#define NTH    512

// ---------------- shared memory layout (float offsets) ---------------------
#define SM_YT   0                      // yT [4][128][36] = 18432
                                       //   overlays: embT [64][34] (P0-P1),
                                       //   zbp [4][512] + ps2 [1024] (P7'-P8)
#define SM_X    18432                  // X [32][128] = 4096
#define SM_A1   22528                  // [4][32][34] = 4352
#define SM_LB   26880                  // 288
#define SM_AS1  27168                  // 128
#define SM_AD1  27296                  // 128
#define SM_AS2  27424                  // 32
#define SM_AD2  27456                  // 32
#define SM_DN2  27488                  // 32
#define SM_CSR  27520                  // 32
#define SM_ZB   27552                  // 512
#define SM_NF   28064
#define SM_NI   (2 * ETOT)             // 576 ints
#define SMEM_BYTES ((SM_NF + SM_NI) * 4)   // 114,560 B -> 2 CTAs/SM

typedef unsigned long long ull;

__device__ float g_wts1[512];
__device__ float g_wtd1[512];
__device__ float g_wt2s[512];
__device__ float g_wt2d[512];

__device__ __forceinline__ ull pk2(float x, float y) {
    ull r; asm("mov.b64 %0, {%1,%2};" : "=l"(r) : "f"(x), "f"(y)); return r;
}
__device__ __forceinline__ ull splat2(float x) { return pk2(x, x); }
__device__ __forceinline__ void upk2(ull p, float& x, float& y) {
    asm("mov.b64 {%0,%1}, %2;" : "=f"(x), "=f"(y) : "l"(p));
}
__device__ __forceinline__ void fma2(ull& d, ull a, ull b) {
    asm("fma.rn.f32x2 %0, %1, %2, %0;" : "+l"(d) : "l"(a), "l"(b));
}
__device__ __forceinline__ void mul2(ull& d, ull b) {
    asm("mul.rn.f32x2 %0, %0, %1;" : "+l"(d) : "l"(b));
}
__device__ __forceinline__ ull add2(ull a, ull b) {
    ull r; asm("add.rn.f32x2 %0, %1, %2;" : "=l"(r) : "l"(a), "l"(b)); return r;
}
__device__ __forceinline__ float dot4(const float4& a, const float4& b) {
    return fmaf(a.x, b.x, fmaf(a.y, b.y, fmaf(a.z, b.z, a.w * b.w)));
}
__device__ __forceinline__ float wredsum(float v) {
    #pragma unroll
    for (int o = 16; o; o >>= 1) v += __shfl_xor_sync(0xffffffffu, v, o);
    return v;
}
__device__ __forceinline__ float elu1(float x) {
    return (x > 0.f) ? x : expm1f(x);
}

// ---------------- pre-kernel: warp-parallel attention-weight projection ----
__global__ void precomp_kernel(const float* __restrict__ W1,
                               const float* __restrict__ as1w,
                               const float* __restrict__ ad1w,
                               const float* __restrict__ W2,
                               const float* __restrict__ as2w,
                               const float* __restrict__ ad2w)
{
    int idx  = blockIdx.x * 4 + (threadIdx.x >> 5);   // 0..1023
    int lane = threadIdx.x & 31;
    if (idx < 512) {
        int h = idx >> 7, k = idx & 127;
        float4 w = ((const float4*)(W1 + k * H4 + h * HID))[lane];
        float4 a = ((const float4*)(as1w + h * HID))[lane];
        float4 d = ((const float4*)(ad1w + h * HID))[lane];
        float s  = wredsum(dot4(w, a));
        float dd = wredsum(dot4(w, d));
        if (lane == 0) { g_wts1[idx] = s; g_wtd1[idx] = dd; }
    } else {
        int k = idx - 512;
        float4 w = ((const float4*)(W2 + k * HID))[lane];
        float4 a = ((const float4*)as2w)[lane];
        float4 d = ((const float4*)ad2w)[lane];
        float s  = wredsum(dot4(w, a));
        float dd = wredsum(dot4(w, d));
        if (lane == 0) { g_wt2s[k] = s; g_wt2d[k] = dd; }
    }
}

__global__ __launch_bounds__(NTH, 2)
void gat_fused_kernel(
    const float* __restrict__ emb,    const float* __restrict__ Wal,
    const float* __restrict__ bal,    const float* __restrict__ lng,
    const float* __restrict__ lnb,    const float* __restrict__ gatel,
    const float* __restrict__ W1,     const float* __restrict__ b1,
    const float* __restrict__ W2,     const float* __restrict__ b2,
    const int*   __restrict__ esrc,   const int*   __restrict__ edst,
    float*       __restrict__ out,    int write_gate)
{
    extern __shared__ float sm[];
    float* yT   = sm + SM_YT;             // [4][128][36]
    float* embT = sm + SM_YT;             // [64][34] overlay
    float* zbp  = sm + SM_YT;             // [4][512] overlay (post-P5)
    float* ps2  = sm + SM_YT + 2048;      // [1024] overlay (post-P5)
    float* X    = sm + SM_X;              // [32][128]
    float* A1   = sm + SM_A1;
    float* lbuf = sm + SM_LB;
    float* as1  = sm + SM_AS1;
    float* ad1  = sm + SM_AD1;
    float* as2  = sm + SM_AS2;
    float* ad2  = sm + SM_AD2;
    float* dn2  = sm + SM_DN2;
    float* csr  = sm + SM_CSR;
    float* zb   = sm + SM_ZB;
    int* sSL = (int*)(sm + SM_NF);
    int* sDL = sSL + ETOT;

    const int g    = blockIdx.x;
    const int tid  = threadIdx.x;
    const int lane = tid & 31;
    const int wid  = tid >> 5;

    // ---------- Phase 0: stage embT + edges, zero accumulators -------------
    {
        float4 v = ((const float4*)emb)[(size_t)g * (FN * DIN / 4) + tid];
        int r  = tid >> 4;
        int c4 = tid & 15;
        embT[(c4 * 4 + 0) * ETPAD + r] = v.x;
        embT[(c4 * 4 + 1) * ETPAD + r] = v.y;
        embT[(c4 * 4 + 2) * ETPAD + r] = v.z;
        embT[(c4 * 4 + 3) * ETPAD + r] = v.w;
    }
    if (tid < 256) {
        sSL[tid] = esrc[g * EPG + tid] - g * FN;
        sDL[tid] = edst[g * EPG + tid] - g * FN;
    }
    if (tid < 32) {
        sSL[EPG + tid] = tid;  sDL[EPG + tid] = tid;   // self loops
        as2[tid] = 0.f; ad2[tid] = 0.f; dn2[tid] = 0.f; csr[tid] = 0.f;
    }
    for (int i = tid; i < (4 * FN * A1PAD) / 4; i += NTH)
        ((float4*)A1)[i] = make_float4(0.f, 0.f, 0.f, 0.f);
    __syncthreads();

    // ---------- Phase 1: align GEMM + in-register LN/gate/logits1 ----------
    {
        ull acc1[4];
        #pragma unroll
        for (int j = 0; j < 4; ++j) acc1[j] = 0ULL;
        const float4* Wp = (const float4*)Wal + lane;
        #pragma unroll 4
        for (int k = 0; k < DIN; ++k) {
            float4 b = Wp[k * 32];
            ull a0 = *(const ull*)(embT + k * ETPAD + wid * 2);
            fma2(acc1[0], a0, splat2(b.x));
            fma2(acc1[1], a0, splat2(b.y));
            fma2(acc1[2], a0, splat2(b.z));
            fma2(acc1[3], a0, splat2(b.w));
        }
        float4 bb = ((const float4*)bal)[lane];
        float4 r0, r1;
        upk2(acc1[0], r0.x, r1.x); upk2(acc1[1], r0.y, r1.y);
        upk2(acc1[2], r0.z, r1.z); upk2(acc1[3], r0.w, r1.w);
        r0.x += bb.x; r0.y += bb.y; r0.z += bb.z; r0.w += bb.w;
        r1.x += bb.x; r1.y += bb.y; r1.z += bb.z; r1.w += bb.w;
        float4 lg = ((const float4*)lng)[lane];
        float4 lb = ((const float4*)lnb)[lane];
        const int row0 = wid * 2;
        float s0 = wredsum(r0.x + r0.y + r0.z + r0.w);
        float q0 = wredsum(dot4(r0, r0));
        float s1 = wredsum(r1.x + r1.y + r1.z + r1.w);
        float q1 = wredsum(dot4(r1, r1));
        float m0 = s0 * (1.f / HID);
        float m1 = s1 * (1.f / HID);
        float rs0 = rsqrtf(q0 * (1.f / HID) - m0 * m0 + 1e-5f);
        float rs1 = rsqrtf(q1 * (1.f / HID) - m1 * m1 + 1e-5f);
        float g0 = 1.f / (1.f + __expf(-gatel[row0]));
        float g1 = 1.f / (1.f + __expf(-gatel[row0 + 1]));
        float4 x0, x1;
        x0.x = ((r0.x - m0) * rs0 * lg.x + lb.x) * g0;
        x0.y = ((r0.y - m0) * rs0 * lg.y + lb.y) * g0;
        x0.z = ((r0.z - m0) * rs0 * lg.z + lb.z) * g0;
        x0.w = ((r0.w - m0) * rs0 * lg.w + lb.w) * g0;
        x1.x = ((r1.x - m1) * rs1 * lg.x + lb.x) * g1;
        x1.y = ((r1.y - m1) * rs1 * lg.y + lb.y) * g1;
        x1.z = ((r1.z - m1) * rs1 * lg.z + lb.z) * g1;
        x1.w = ((r1.w - m1) * rs1 * lg.w + lb.w) * g1;
        ((float4*)(X + row0 * XPAD))[lane]       = x0;
        ((float4*)(X + (row0 + 1) * XPAD))[lane] = x1;
        #pragma unroll
        for (int h = 0; h < NHEADS; ++h) {
            float4 ws = ((const float4*)g_wts1)[h * 32 + lane];
            float4 wd = ((const float4*)g_wtd1)[h * 32 + lane];
            float a0s = wredsum(dot4(x0, ws));
            float a0d = wredsum(dot4(x0, wd));
            float a1s = wredsum(dot4(x1, ws));
            float a1d = wredsum(dot4(x1, wd));
            if (lane == 0) {
                as1[row0 * 4 + h] = a0s;       ad1[row0 * 4 + h] = a0d;
                as1[(row0 + 1) * 4 + h] = a1s; ad1[(row0 + 1) * 4 + h] = a1d;
            }
        }
    }
    __syncthreads();

    // ---------- Phase 3: edge pass 1 -> dense A1 ---------------------------
    {
        int h = tid & 3;
        for (int e = tid >> 2; e < ETOT; e += 128) {
            int s = sSL[e], d = sDL[e];
            float l = as1[s * 4 + h] + ad1[d * 4 + h];
            l = (l > 0.f) ? l : 0.2f * l;
            atomicAdd(&A1[(h * FN + s) * A1PAD + d], __expf(l));
        }
    }
    __syncthreads();

    // ====== Phase 4+5 FUSED (producer == consumer warp; no block barrier) ==
    // Warp identity: h = wid>>2 (head), dg = wid&3 (d-octet == row-octet rg).
    // P4 writes yT[h][all k][dg octet]; P5 reads exactly that region.
    ull acc[4][4];          // after P5: h1 rows (dg*8+2p,+1) x cols h*128+lane*4+j
    {
        const int h  = wid >> 2;
        const int dg = wid & 3;

        // ---- P4: y = A1n^T @ x for (h, d-octet dg), all 128 k ------------
        int myd = dg * 8 + (lane & 7);
        float csum = 0.f;
        #pragma unroll 8
        for (int s = 0; s < FN; ++s) csum += A1[(h * FN + s) * A1PAD + myd];
        float myinv = __fdividef(1.f, csum);
        #pragma unroll
        for (int q = 0; q < 4; ++q)
            #pragma unroll
            for (int dp = 0; dp < 4; ++dp) acc[q][dp] = 0ULL;
        #pragma unroll 2
        for (int s = 0; s < FN; ++s) {
            const ull* ar = (const ull*)(A1 + (h * FN + s) * A1PAD + dg * 8);
            ull a0 = ar[0], a1 = ar[1], a2 = ar[2], a3 = ar[3];
            const float* xr = X + s * XPAD + lane;
            ull x0 = splat2(xr[0]);
            ull x1 = splat2(xr[32]);
            ull x2 = splat2(xr[64]);
            ull x3 = splat2(xr[96]);
            fma2(acc[0][0], a0, x0); fma2(acc[0][1], a1, x0);
            fma2(acc[0][2], a2, x0); fma2(acc[0][3], a3, x0);
            fma2(acc[1][0], a0, x1); fma2(acc[1][1], a1, x1);
            fma2(acc[1][2], a2, x1); fma2(acc[1][3], a3, x1);
            fma2(acc[2][0], a0, x2); fma2(acc[2][1], a1, x2);
            fma2(acc[2][2], a2, x2); fma2(acc[2][3], a3, x2);
            fma2(acc[3][0], a0, x3); fma2(acc[3][1], a1, x3);
            fma2(acc[3][2], a2, x3); fma2(acc[3][3], a3, x3);
        }
        ull iv[4];
        #pragma unroll
        for (int dp = 0; dp < 4; ++dp) {
            float i0 = __shfl_sync(0xffffffffu, myinv, 2 * dp);
            float i1 = __shfl_sync(0xffffffffu, myinv, 2 * dp + 1);
            iv[dp] = pk2(i0, i1);
        }
        #pragma unroll
        for (int q = 0; q < 4; ++q) {
            int k = lane + 32 * q;
            float* yb = yT + (h * HID + k) * YTPAD + dg * 8;
            #pragma unroll
            for (int dp = 0; dp < 4; ++dp) mul2(acc[q][dp], iv[dp]);
            ulonglong2 v01, v23;
            v01.x = acc[q][0]; v01.y = acc[q][1];
            v23.x = acc[q][2]; v23.y = acc[q][3];
            ((ulonglong2*)yb)[0] = v01;
            ((ulonglong2*)yb)[1] = v23;
        }
        __syncwarp();        // cross-lane visibility of this warp's yT slice

        // ---- P5: h1 rows dg*8..+7 = ELU(y @ W1[:, h-block] + b1) ---------
        #pragma unroll
        for (int p = 0; p < 4; ++p)
            #pragma unroll
            for (int j = 0; j < 4; ++j) acc[p][j] = 0ULL;
        const float4* Wp = (const float4*)W1 + h * 32 + lane;
        const float* yh = yT + h * HID * YTPAD + dg * 8;
        #pragma unroll 2
        for (int k = 0; k < HID; ++k) {
            float4 w = Wp[k * 128];
            ull b0 = splat2(w.x), b1v = splat2(w.y);
            ull b2v = splat2(w.z), b3 = splat2(w.w);
            const ulonglong2* yp = (const ulonglong2*)(yh + k * YTPAD);
            ulonglong2 y01 = yp[0];
            ulonglong2 y23 = yp[1];
            fma2(acc[0][0], y01.x, b0); fma2(acc[0][1], y01.x, b1v);
            fma2(acc[0][2], y01.x, b2v); fma2(acc[0][3], y01.x, b3);
            fma2(acc[1][0], y01.y, b0); fma2(acc[1][1], y01.y, b1v);
            fma2(acc[1][2], y01.y, b2v); fma2(acc[1][3], y01.y, b3);
            fma2(acc[2][0], y23.x, b0); fma2(acc[2][1], y23.x, b1v);
            fma2(acc[2][2], y23.x, b2v); fma2(acc[2][3], y23.x, b3);
            fma2(acc[3][0], y23.y, b0); fma2(acc[3][1], y23.y, b1v);
            fma2(acc[3][2], y23.y, b2v); fma2(acc[3][3], y23.y, b3);
        }
        float4 bb  = ((const float4*)b1)[h * 32 + lane];
        float4 w2s = ((const float4*)g_wt2s)[h * 32 + lane];
        float4 w2d = ((const float4*)g_wt2d)[h * 32 + lane];
        #pragma unroll
        for (int p = 0; p < 4; ++p) {
            int d0 = dg * 8 + p * 2;
            float4 r0, r1;
            upk2(acc[p][0], r0.x, r1.x); upk2(acc[p][1], r0.y, r1.y);
            upk2(acc[p][2], r0.z, r1.z); upk2(acc[p][3], r0.w, r1.w);
            r0.x = elu1(r0.x + bb.x); r0.y = elu1(r0.y + bb.y);
            r0.z = elu1(r0.z + bb.z); r0.w = elu1(r0.w + bb.w);
            r1.x = elu1(r1.x + bb.x); r1.y = elu1(r1.y + bb.y);
            r1.z = elu1(r1.z + bb.z); r1.w = elu1(r1.w + bb.w);
            acc[p][0] = pk2(r0.x, r1.x);
            acc[p][1] = pk2(r0.y, r1.y);
            acc[p][2] = pk2(r0.z, r1.z);
            acc[p][3] = pk2(r0.w, r1.w);
            float s0  = wredsum(dot4(r0, w2s));
            float d0s = wredsum(dot4(r0, w2d));
            float s1  = wredsum(dot4(r1, w2s));
            float d1s = wredsum(dot4(r1, w2d));
            if (lane == 0) {
                atomicAdd(&as2[d0], s0);
                atomicAdd(&ad2[d0], d0s);
                atomicAdd(&as2[d0 + 1], s1);
                atomicAdd(&ad2[d0 + 1], d1s);
            }
        }
    }
    __syncthreads();

    // ---------- Phase 6: edge pass 2 -> csr (merged iv2) -------------------
    if (tid < ETOT) {
        int s = sSL[tid], d = sDL[tid];
        float l = as2[s] + ad2[d];
        l = (l > 0.f) ? l : 0.2f * l;
        float ex = __expf(l);
        lbuf[tid] = ex;
        atomicAdd(&dn2[d], ex);
    }
    __syncthreads();
    if (tid < ETOT) {
        int s = sSL[tid], d = sDL[tid];
        atomicAdd(&csr[s], lbuf[tid] * __fdividef(1.f, dn2[d] * (float)FN));
    }
    __syncthreads();

    // ---------- Phase 7': zb partials from register-resident h1 ------------
    {
        const int h  = wid >> 2;
        const int rg = wid & 3;
        ull csrp[4];
        #pragma unroll
        for (int p = 0; p < 4; ++p)
            csrp[p] = pk2(csr[rg * 8 + 2 * p], csr[rg * 8 + 2 * p + 1]);
        float4 zp4;
        float* zv = &zp4.x;
        #pragma unroll
        for (int j = 0; j < 4; ++j) {
            ull za = 0ULL;
            #pragma unroll
            for (int p = 0; p < 4; ++p) fma2(za, csrp[p], acc[p][j]);
            float lo, hi;
            upk2(za, lo, hi);
            zv[j] = lo + hi;
        }
        ((float4*)(zbp + rg * 512 + h * HID))[lane] = zp4;
    }
    __syncthreads();
    zb[tid] = zbp[tid] + zbp[512 + tid] + zbp[1024 + tid] + zbp[1536 + tid];
    __syncthreads();

    // ---------- Phase 8: out = zbar @ W2 + b2 (f32x2 col-pairs, 8 ks) ------
    {
        const int ks = tid >> 6;             // 8 k-splits of 64
        const int cp = tid & 63;             // column pair
        const float* w2 = W2 + (ks * 64) * HID + cp * 2;
        const float* zp = zb + ks * 64;
        ull a0 = 0ULL, a1 = 0ULL, a2 = 0ULL, a3 = 0ULL;
        #pragma unroll 4
        for (int k = 0; k < 64; k += 4) {
            fma2(a0, splat2(zp[k + 0]), *(const ull*)(w2 + (k + 0) * HID));
            fma2(a1, splat2(zp[k + 1]), *(const ull*)(w2 + (k + 1) * HID));
            fma2(a2, splat2(zp[k + 2]), *(const ull*)(w2 + (k + 2) * HID));
            fma2(a3, splat2(zp[k + 3]), *(const ull*)(w2 + (k + 3) * HID));
        }
        ull tot = add2(add2(a0, a1), add2(a2, a3));
        *(ull*)(ps2 + tid * 2) = tot;        // ps2[ks*128 + c] = partial(c)
    }
    __syncthreads();
    if (tid < HID) {
        float tot = 0.f;
        #pragma unroll
        for (int q = 0; q < 8; ++q) tot += ps2[q * 128 + tid];
        out[(size_t)g * HID + tid] = tot + b2[tid];
    }
    if (write_gate && g == 0 && tid < FN) {
        out[(size_t)BGRAPH * HID + tid] = 1.f / (1.f + __expf(-gatel[tid]));
    }
}

extern "C" void kernel_launch(void* const* d_in, const int* in_sizes, int n_in,
                              void* d_out, int out_size)
{
    const float* emb   = (const float*)d_in[0];
    const float* Wal   = (const float*)d_in[1];
    const float* bal   = (const float*)d_in[2];
    const float* lng   = (const float*)d_in[3];
    const float* lnb   = (const float*)d_in[4];
    const float* gatel = (const float*)d_in[5];
    const float* W1    = (const float*)d_in[6];
    const float* as1w  = (const float*)d_in[7];
    const float* ad1w  = (const float*)d_in[8];
    const float* b1    = (const float*)d_in[9];
    const float* W2    = (const float*)d_in[10];
    const float* as2w  = (const float*)d_in[11];
    const float* ad2w  = (const float*)d_in[12];
    const float* b2    = (const float*)d_in[13];
    const int*   ei    = (const int*)d_in[14];

    const int Et = in_sizes[14] / 2;
    const int* esrc = ei;
    const int* edst = ei + Et;
    const int write_gate = (out_size >= BGRAPH * HID + FN) ? 1 : 0;

    cudaFuncSetAttribute(gat_fused_kernel,
                         cudaFuncAttributeMaxDynamicSharedMemorySize, SMEM_BYTES);

    precomp_kernel<<<256, 128>>>(W1, as1w, ad1w, W2, as2w, ad2w);
    gat_fused_kernel<<<BGRAPH, NTH, SMEM_BYTES>>>(
        emb, Wal, bal, lng, lnb, gatel,
        W1, b1, W2, b2,
        esrc, edst, (float*)d_out, write_gate);
}